// round 11
// baseline (speedup 1.0000x reference)
#include <cuda_runtime.h>
#include <cstdint>

#define HH 56
#define WW 56
#define HM 50
#define WM 50
#define NPLANES 16384            // 64 * 256
#define COUNT_M 51380224ull      // 64*256*56*56
#define NSLOTS 512

// Scratch (allocation-free). g_partial is zero at load; k_finalize resets it
// after reading, so every graph replay sees zeros again.
__device__ unsigned g_partial[NSLOTS];
__device__ float g_scale;
__device__ unsigned long long g_dmask[NPLANES * HH];   // 7.34 MB packed dilated mask

// One CTA (128 thr) per plane. Front-batched streaming loads (MLP=5), rare
// shared atomicOr to build 50 row bitmasks, separable 7x7 bit dilation
// (OR of shifts 0..6 == window [o-6,o], matching the pad=6 reduce_window).
__global__ __launch_bounds__(128) void k_pass1(const float* __restrict__ u,
                                               const float* __restrict__ gamma) {
    __shared__ unsigned long long row[HM];   // seed mask, then dilated in place
    __shared__ unsigned wsum[2];
    const int plane = blockIdx.x;
    const int tid = threadIdx.x;
    const float g = __ldg(gamma);

    if (tid < HM) row[tid] = 0ull;
    __syncthreads();

    // 625 float4 per plane; 5 batched loads per thread (last predicated).
    const float4* u4 = (const float4*)(u + (size_t)plane * (HM * WM));
    float4 v[5];
    const bool p4 = (tid < 625 - 512);
    #pragma unroll
    for (int k = 0; k < 4; ++k) v[k] = __ldcs(u4 + tid + k * 128);
    if (p4) v[4] = __ldcs(u4 + tid + 512);

    #pragma unroll
    for (int k = 0; k < 5; ++k) {
        if (k == 4 && !p4) break;
        const int e = (tid + k * 128) * 4;
        if (v[k].x < g) atomicOr(&row[ e      / WM], 1ull << ( e      % WM));
        if (v[k].y < g) atomicOr(&row[(e + 1) / WM], 1ull << ((e + 1) % WM));
        if (v[k].z < g) atomicOr(&row[(e + 2) / WM], 1ull << ((e + 2) % WM));
        if (v[k].w < g) atomicOr(&row[(e + 3) / WM], 1ull << ((e + 3) % WM));
    }
    __syncthreads();

    // Horizontal dilation, in place (rows independent).
    if (tid < HM) {
        unsigned long long m  = row[tid];
        unsigned long long t1 = m  | (m  << 1);
        unsigned long long t2 = t1 | (t1 << 2);
        row[tid] = t2 | (t2 << 3);                 // shifts 0..6, bits stay < 56
    }
    __syncthreads();

    // Vertical dilation: output row o = OR of row[max(0,o-6) .. min(o,49)]
    unsigned v1 = 0;
    if (tid < HH) {
        int lo = tid - 6; if (lo < 0) lo = 0;
        int hi = (tid < HM) ? tid : (HM - 1);
        unsigned long long d = 0ull;
        #pragma unroll 1
        for (int r = lo; r <= hi; ++r) d |= row[r];
        g_dmask[(size_t)plane * HH + tid] = d;
        v1 = (unsigned)__popcll(d);
    }
    if (tid < 64) {
        #pragma unroll
        for (int off = 16; off; off >>= 1) v1 += __shfl_down_sync(0xffffffffu, v1, off);
        if ((tid & 31) == 0) wsum[tid >> 5] = v1;
    }
    __syncthreads();
    if (tid == 0)
        atomicAdd(&g_partial[plane & (NSLOTS - 1)], wsum[0] + wsum[1]);  // spread slots
}

// One block: sum the 512 slots, compute scale (f32, like the jnp reference),
// reset slots for the next replay.
__global__ __launch_bounds__(NSLOTS) void k_finalize() {
    __shared__ unsigned s[NSLOTS / 32];
    const int tid = threadIdx.x;
    unsigned v = g_partial[tid];
    g_partial[tid] = 0u;
    #pragma unroll
    for (int off = 16; off; off >>= 1) v += __shfl_down_sync(0xffffffffu, v, off);
    if ((tid & 31) == 0) s[tid >> 5] = v;
    __syncthreads();
    if (tid < 32) {
        unsigned w = (tid < NSLOTS / 32) ? s[tid] : 0u;
        #pragma unroll
        for (int off = 8; off; off >>= 1) w += __shfl_down_sync(0xffffffffu, w, off);
        if (tid == 0)
            g_scale = (float)COUNT_M / (float)(COUNT_M - (unsigned long long)w);
    }
}

// Elementwise apply, 2x float4 per thread, streaming loads/stores.
__global__ __launch_bounds__(256) void k_pass2(const float* __restrict__ x,
                                               float* __restrict__ out) {
    const unsigned i40 = blockIdx.x * 512u + threadIdx.x;
    const unsigned i41 = i40 + 256u;
    const float s = g_scale;

    const unsigned p0 = i40 / 784u, r0q = i40 - p0 * 784u;
    const unsigned row0 = r0q / 14u, w40 = r0q - row0 * 14u;
    const unsigned p1 = i41 / 784u, r1q = i41 - p1 * 784u;
    const unsigned row1 = r1q / 14u, w41 = r1q - row1 * 14u;

    const unsigned long long d0 = __ldg(&g_dmask[p0 * HH + row0]);
    const unsigned long long d1 = __ldg(&g_dmask[p1 * HH + row1]);
    const float4 x0 = __ldcs(((const float4*)x) + i40);
    const float4 x1 = __ldcs(((const float4*)x) + i41);

    const unsigned n0 = (unsigned)(d0 >> (w40 * 4u)) & 0xFu;
    const unsigned n1 = (unsigned)(d1 >> (w41 * 4u)) & 0xFu;
    float4 o0, o1;
    o0.x = (n0 & 1u) ? 0.f : x0.x * s;
    o0.y = (n0 & 2u) ? 0.f : x0.y * s;
    o0.z = (n0 & 4u) ? 0.f : x0.z * s;
    o0.w = (n0 & 8u) ? 0.f : x0.w * s;
    o1.x = (n1 & 1u) ? 0.f : x1.x * s;
    o1.y = (n1 & 2u) ? 0.f : x1.y * s;
    o1.z = (n1 & 4u) ? 0.f : x1.z * s;
    o1.w = (n1 & 8u) ? 0.f : x1.w * s;
    __stcs(((float4*)out) + i40, o0);
    __stcs(((float4*)out) + i41, o1);
}

extern "C" void kernel_launch(void* const* d_in, const int* in_sizes, int n_in,
                              void* d_out, int out_size) {
    const float* x     = (const float*)d_in[0];
    const float* u     = (const float*)d_in[1];
    const float* gamma = (const float*)d_in[2];
    float* out = (float*)d_out;

    k_pass1<<<NPLANES, 128>>>(u, gamma);
    k_finalize<<<1, NSLOTS>>>();
    k_pass2<<<(unsigned)(COUNT_M / 4ull / 512ull), 256>>>(x, out);   // 25088 blocks
}

// round 12
// speedup vs baseline: 1.2831x; 1.2831x over previous
#include <cuda_runtime.h>
#include <cstdint>

#define HH 56
#define WW 56
#define HM 50
#define WM 50
#define NPLANES 16384            // 64 * 256
#define COUNT_M 51380224ull      // 64*256*56*56
#define NSLOTS 512

// Scratch (allocation-free). g_partial is zero at load; k_finalize resets it
// after reading, so every graph replay sees zeros again.
__device__ unsigned g_partial[NSLOTS];
__device__ float g_scale;
__device__ unsigned long long g_dmask[NPLANES * HH];   // 7.34 MB packed dilated mask

// One CTA (128 thr) per plane. Front-batched streaming loads (MLP=5); per
// float4, a 4-bit nibble of compares guards ALL slow work (div/shift/atomic),
// so the 92.5%-common case is ~7 instructions. Separable 7x7 bit dilation
// (OR of shifts 0..6 == window [o-6,o], matching the pad=6 reduce_window).
__global__ __launch_bounds__(128) void k_pass1(const float* __restrict__ u,
                                               const float* __restrict__ gamma) {
    __shared__ unsigned long long row[HM];   // seed mask, then dilated in place
    __shared__ unsigned wsum[2];
    const int plane = blockIdx.x;
    const int tid = threadIdx.x;
    const float g = __ldg(gamma);

    if (tid < HM) row[tid] = 0ull;
    __syncthreads();

    // 625 float4 per plane; 5 batched loads per thread (last predicated).
    const float4* u4 = (const float4*)(u + (size_t)plane * (HM * WM));
    float4 v[5];
    const bool p4 = (tid < 625 - 512);
    #pragma unroll
    for (int k = 0; k < 4; ++k) v[k] = __ldcs(u4 + tid + k * 128);
    if (p4) v[4] = __ldcs(u4 + tid + 512);

    #pragma unroll
    for (int k = 0; k < 5; ++k) {
        if (k == 4 && !p4) break;
        const unsigned nib = (unsigned)(v[k].x < g)
                           | ((unsigned)(v[k].y < g) << 1)
                           | ((unsigned)(v[k].z < g) << 2)
                           | ((unsigned)(v[k].w < g) << 3);
        if (nib) {                                    // rare (~7.5%)
            const int e = (tid + k * 128) * 4;
            const int r = e / WM;
            const int c = e - r * WM;
            const unsigned long long m = (unsigned long long)nib << c;  // c<=49: fits
            const unsigned long long lo = m & ((1ull << WM) - 1ull);
            const unsigned long long hi = m >> WM;
            if (lo) atomicOr(&row[r], lo);
            if (hi) atomicOr(&row[r + 1], hi);        // only c in {47,48,49}; r+1<=49
        }
    }
    __syncthreads();

    // Horizontal dilation, in place (rows independent).
    if (tid < HM) {
        unsigned long long m  = row[tid];
        unsigned long long t1 = m  | (m  << 1);
        unsigned long long t2 = t1 | (t1 << 2);
        row[tid] = t2 | (t2 << 3);                 // shifts 0..6, bits stay < 56
    }
    __syncthreads();

    // Vertical dilation: output row o = OR of row[max(0,o-6) .. min(o,49)]
    unsigned v1 = 0;
    if (tid < HH) {
        int lo = tid - 6; if (lo < 0) lo = 0;
        int hi = (tid < HM) ? tid : (HM - 1);
        unsigned long long d = 0ull;
        #pragma unroll 1
        for (int r = lo; r <= hi; ++r) d |= row[r];
        g_dmask[(size_t)plane * HH + tid] = d;
        v1 = (unsigned)__popcll(d);
    }
    if (tid < 64) {
        #pragma unroll
        for (int off = 16; off; off >>= 1) v1 += __shfl_down_sync(0xffffffffu, v1, off);
        if ((tid & 31) == 0) wsum[tid >> 5] = v1;
    }
    __syncthreads();
    if (tid == 0)
        atomicAdd(&g_partial[plane & (NSLOTS - 1)], wsum[0] + wsum[1]);  // spread slots
}

// One block: sum the 512 slots, compute scale (f32, like the jnp reference),
// reset slots for the next replay.
__global__ __launch_bounds__(NSLOTS) void k_finalize() {
    __shared__ unsigned s[NSLOTS / 32];
    const int tid = threadIdx.x;
    unsigned v = g_partial[tid];
    g_partial[tid] = 0u;
    #pragma unroll
    for (int off = 16; off; off >>= 1) v += __shfl_down_sync(0xffffffffu, v, off);
    if ((tid & 31) == 0) s[tid >> 5] = v;
    __syncthreads();
    if (tid < 32) {
        unsigned w = (tid < NSLOTS / 32) ? s[tid] : 0u;
        #pragma unroll
        for (int off = 8; off; off >>= 1) w += __shfl_down_sync(0xffffffffu, w, off);
        if (tid == 0)
            g_scale = (float)COUNT_M / (float)(COUNT_M - (unsigned long long)w);
    }
}

// Elementwise apply, 2x float4 per thread, streaming loads/stores.
__global__ __launch_bounds__(256) void k_pass2(const float* __restrict__ x,
                                               float* __restrict__ out) {
    const unsigned i40 = blockIdx.x * 512u + threadIdx.x;
    const unsigned i41 = i40 + 256u;
    const float s = g_scale;

    const unsigned p0 = i40 / 784u, r0q = i40 - p0 * 784u;
    const unsigned row0 = r0q / 14u, w40 = r0q - row0 * 14u;
    const unsigned p1 = i41 / 784u, r1q = i41 - p1 * 784u;
    const unsigned row1 = r1q / 14u, w41 = r1q - row1 * 14u;

    const unsigned long long d0 = __ldg(&g_dmask[p0 * HH + row0]);
    const unsigned long long d1 = __ldg(&g_dmask[p1 * HH + row1]);
    const float4 x0 = __ldcs(((const float4*)x) + i40);
    const float4 x1 = __ldcs(((const float4*)x) + i41);

    const unsigned n0 = (unsigned)(d0 >> (w40 * 4u)) & 0xFu;
    const unsigned n1 = (unsigned)(d1 >> (w41 * 4u)) & 0xFu;
    float4 o0, o1;
    o0.x = (n0 & 1u) ? 0.f : x0.x * s;
    o0.y = (n0 & 2u) ? 0.f : x0.y * s;
    o0.z = (n0 & 4u) ? 0.f : x0.z * s;
    o0.w = (n0 & 8u) ? 0.f : x0.w * s;
    o1.x = (n1 & 1u) ? 0.f : x1.x * s;
    o1.y = (n1 & 2u) ? 0.f : x1.y * s;
    o1.z = (n1 & 4u) ? 0.f : x1.z * s;
    o1.w = (n1 & 8u) ? 0.f : x1.w * s;
    __stcs(((float4*)out) + i40, o0);
    __stcs(((float4*)out) + i41, o1);
}

extern "C" void kernel_launch(void* const* d_in, const int* in_sizes, int n_in,
                              void* d_out, int out_size) {
    const float* x     = (const float*)d_in[0];
    const float* u     = (const float*)d_in[1];
    const float* gamma = (const float*)d_in[2];
    float* out = (float*)d_out;

    k_pass1<<<NPLANES, 128>>>(u, gamma);
    k_finalize<<<1, NSLOTS>>>();
    k_pass2<<<(unsigned)(COUNT_M / 4ull / 512ull), 256>>>(x, out);   // 25088 blocks
}